// round 7
// baseline (speedup 1.0000x reference)
#include <cuda_runtime.h>
#include <cuda_fp16.h>
#include <math.h>
#include <stdint.h>

#define BATCH   1024
#define NTOK    64
#define DIM     512
#define HEADS   16
#define HDIM    32
#define NW      64
#define ROWS    (BATCH * NTOK)      // 65536
#define QKVCOLS (3 * DIM)           // 1536

// ---------------- device scratch ----------------
__device__ __align__(16) float g_qkv[(size_t)ROWS * QKVCOLS];
__device__ __align__(16) char  g_xhi[(size_t)ROWS * DIM];
__device__ __align__(16) char  g_xlo[(size_t)ROWS * DIM];
__device__ __align__(16) char  g_whi[(size_t)QKVCOLS * DIM];
__device__ __align__(16) char  g_wlo[(size_t)QKVCOLS * DIM];
__device__ __align__(16) char  g_phi[(size_t)DIM * DIM];
__device__ __align__(16) char  g_plo[(size_t)DIM * DIM];
__device__ __align__(16) char  g_ahi[(size_t)ROWS * DIM];
__device__ __align__(16) char  g_alo[(size_t)ROWS * DIM];
__device__ float g_bias_table[225 * HEADS];
__device__ float g_rel_bias[HEADS * NTOK * NTOK];
__device__ float g_scale[HEADS];

// ---------------- helpers ----------------
__device__ __forceinline__ uint32_t smem_u32(const void* p) {
    uint32_t a;
    asm("{ .reg .u64 t; cvta.to.shared.u64 t, %1; cvt.u32.u64 %0, t; }" : "=r"(a) : "l"(p));
    return a;
}

#define LDSM4(r0,r1,r2,r3, addr) \
    asm volatile("ldmatrix.sync.aligned.m8n8.x4.shared.b16 {%0,%1,%2,%3}, [%4];" \
        : "=r"(r0),"=r"(r1),"=r"(r2),"=r"(r3) : "r"(addr))

#define MMA_S8(d, a, b) \
    asm volatile("mma.sync.aligned.m16n8k32.row.col.s32.s8.s8.s32 " \
        "{%0,%1,%2,%3}, {%4,%5,%6,%7}, {%8,%9}, {%0,%1,%2,%3};" \
        : "+r"(d[0]),"+r"(d[1]),"+r"(d[2]),"+r"(d[3]) \
        : "r"(a[0]),"r"(a[1]),"r"(a[2]),"r"(a[3]),"r"(b[0]),"r"(b[1]))

#define CP16(dst, src) \
    asm volatile("cp.async.ca.shared.global [%0], [%1], 16;" :: "r"(dst), "l"(src))
#define CP_COMMIT() asm volatile("cp.async.commit_group;" ::: "memory")
#define CP_WAIT1()  asm volatile("cp.async.wait_group 1;" ::: "memory")

// split fp32 into two int8 limbs of a 16-bit fixed-point value (scale = 2^s)
__device__ __forceinline__ void q16_split(float x, float scale, char& h, char& l) {
    int q = __float2int_rn(x * scale);
    q = max(-32512, min(32511, q));
    int qh = (q + 128) >> 8;
    int ql = q - (qh << 8);
    h = (char)qh;
    l = (char)ql;
}

// ---------------- quantize fp32 -> int8 hi/lo limbs ----------------
__global__ void quant_i8(const float* __restrict__ in,
                         char* __restrict__ hi, char* __restrict__ lo,
                         int n4, float scale)
{
    int i = blockIdx.x * blockDim.x + threadIdx.x;
    if (i >= n4) return;
    float4 v = ((const float4*)in)[i];
    float x[4] = {v.x, v.y, v.z, v.w};
    char h[4], l[4];
    #pragma unroll
    for (int j = 0; j < 4; j++) q16_split(x[j], scale, h[j], l[j]);
    *(uint32_t*)(hi + 4*(size_t)i) = *(uint32_t*)h;
    *(uint32_t*)(lo + 4*(size_t)i) = *(uint32_t*)l;
}

// ---------------- CPB MLP ----------------
__global__ void cpb_mlp_kernel(const float* __restrict__ tbl,
                               const float* __restrict__ w1,
                               const float* __restrict__ b1,
                               const float* __restrict__ w2)
{
    int i = blockIdx.x, j = threadIdx.x;
    __shared__ float hid[512];
    float hv = tbl[i*2+0] * w1[j*2+0] + tbl[i*2+1] * w1[j*2+1] + b1[j];
    hid[j] = fmaxf(hv, 0.0f);
    __syncthreads();
    int warp = j >> 5, lane = j & 31;
    float s = 0.0f;
    #pragma unroll
    for (int c = lane; c < 512; c += 32) s += hid[c] * w2[warp*512 + c];
    #pragma unroll
    for (int off = 16; off > 0; off >>= 1) s += __shfl_xor_sync(0xffffffffu, s, off);
    if (lane == 0) g_bias_table[i*HEADS + warp] = s;
}

__global__ void cpb_expand_kernel(const int* __restrict__ idx,
                                  const float* __restrict__ logit_scale)
{
    int g = blockIdx.x * 256 + threadIdx.x;
    int h = g >> 12, nm = g & 4095;
    float v = g_bias_table[idx[nm]*HEADS + h];
    g_rel_bias[g] = 16.0f / (1.0f + expf(-v));
    if (g < HEADS) g_scale[g] = expf(fminf(logit_scale[g], 4.60517018598809136804f));
}

// ---------------------------------------------------------------------------
// int8 2-limb EXACT GEMM (NT): C = dequant( A16 @ B16^T ) + bias, K=512.
// A16 = 256*Ahi+Alo (x at 2^12), B16 = 256*Bhi+Blo (w at 2^18).
// C = 2^-14*(Ahi@Bhi) + 2^-22*(Ahi@Blo + Alo@Bhi) + 2^-30*(Alo@Blo)
// BM=128 BN=64 BK=64. 256 thr = 8 warps (4m x 2n), warp 32x32.
// 3-stage cp.async pipeline; rows padded to 80B.
// ---------------------------------------------------------------------------
#define A_B 10240
#define B_B 5120
#define STG (2*A_B + 2*B_B)     // 30720
#define GEMM_SMEM (3 * STG)     // 92160

template <int MODE>   // 0: qkv bias (q|0|v), 1: proj bias
__global__ __launch_bounds__(256, 1) void gemm_i8(
    const char* __restrict__ Ah, const char* __restrict__ Al,
    const char* __restrict__ Bh, const char* __restrict__ Bl,
    const float* __restrict__ bias0, const float* __restrict__ bias1,
    float* __restrict__ C, int N)
{
    extern __shared__ char smem[];

    const int tid  = threadIdx.x;
    const int bm   = blockIdx.y * 128;
    const int bn   = blockIdx.x * 64;
    const int wid  = tid >> 5, lane = tid & 31;
    const int wm   = (wid & 3) * 32;
    const int wn   = (wid >> 2) * 32;

    const uint32_t sbase = smem_u32(smem);

    int acc0[2][4][4], acc1[2][4][4], acc2[2][4][4];
    #pragma unroll
    for (int a = 0; a < 2; a++)
        #pragma unroll
        for (int b = 0; b < 4; b++)
            #pragma unroll
            for (int c = 0; c < 4; c++) { acc0[a][b][c] = 0; acc1[a][b][c] = 0; acc2[a][b][c] = 0; }

    auto load_stage = [&](int kt, int buf) {
        const uint32_t sb = sbase + buf * STG;
        const int k0 = kt * 64;
        #pragma unroll
        for (int i = 0; i < 2; i++) {
            int idx = tid * 2 + i;          // 0..511
            int row = idx >> 2, q = idx & 3;
            uint32_t d = sb + (uint32_t)(row * 80 + q * 16);
            const char* sh = Ah + (size_t)(bm + row) * 512 + k0 + q * 16;
            const char* sl = Al + (size_t)(bm + row) * 512 + k0 + q * 16;
            CP16(d, sh);
            CP16(d + A_B, sl);
        }
        {
            int row = tid >> 2, q = tid & 3;
            uint32_t d = sb + 2*A_B + (uint32_t)(row * 80 + q * 16);
            const char* sh = Bh + (size_t)(bn + row) * 512 + k0 + q * 16;
            const char* sl = Bl + (size_t)(bn + row) * 512 + k0 + q * 16;
            CP16(d, sh);
            CP16(d + B_B, sl);
        }
        CP_COMMIT();
    };

    load_stage(0, 0);
    load_stage(1, 1);

    for (int kt = 0; kt < 8; kt++) {
        const int buf = kt % 3;
        CP_WAIT1();
        __syncthreads();

        if (kt + 2 < 8) load_stage(kt + 2, (kt + 2) % 3);
        else CP_COMMIT();

        const uint32_t sb  = sbase + buf * STG;
        const uint32_t aAh = sb;
        const uint32_t aAl = sb + A_B;
        const uint32_t aBh = sb + 2*A_B;
        const uint32_t aBl = sb + 2*A_B + B_B;

        #pragma unroll
        for (int ks = 0; ks < 2; ks++) {
            const int kb = ks * 32;   // bytes
            uint32_t ah[2][4], al[2][4], bh[4][2], bl[4][2];
            #pragma unroll
            for (int mt = 0; mt < 2; mt++) {
                int row = wm + mt*16 + (lane & 15);
                int col = kb + (lane >> 4) * 16;
                uint32_t off = (uint32_t)(row*80 + col);
                LDSM4(ah[mt][0], ah[mt][1], ah[mt][2], ah[mt][3], aAh + off);
                LDSM4(al[mt][0], al[mt][1], al[mt][2], al[mt][3], aAl + off);
            }
            #pragma unroll
            for (int np = 0; np < 2; np++) {
                int g = lane >> 3;
                int row = wn + np*16 + (lane & 7) + ((g >> 1) & 1) * 8;
                int col = kb + (g & 1) * 16;
                uint32_t off = (uint32_t)(row*80 + col);
                LDSM4(bh[2*np][0], bh[2*np][1], bh[2*np+1][0], bh[2*np+1][1], aBh + off);
                LDSM4(bl[2*np][0], bl[2*np][1], bl[2*np+1][0], bl[2*np+1][1], aBl + off);
            }
            #pragma unroll
            for (int mt = 0; mt < 2; mt++)
                #pragma unroll
                for (int nt = 0; nt < 4; nt++) {
                    MMA_S8(acc0[mt][nt], ah[mt], bh[nt]);
                    MMA_S8(acc1[mt][nt], ah[mt], bl[nt]);
                    MMA_S8(acc1[mt][nt], al[mt], bh[nt]);
                    MMA_S8(acc2[mt][nt], al[mt], bl[nt]);
                }
        }
        __syncthreads();
    }

    // ---- epilogue: exact dequant + bias ----
    const float f0 = 6.103515625e-05f;          // 2^-14
    const float f1 = 2.384185791015625e-07f;    // 2^-22
    const float f2 = 9.313225746154785e-10f;    // 2^-30
    #pragma unroll
    for (int mt = 0; mt < 2; mt++) {
        #pragma unroll
        for (int nt = 0; nt < 4; nt++) {
            int row = bm + wm + mt*16 + (lane >> 2);
            int col = bn + wn + nt*8 + (lane & 3)*2;
            float b0, b1;
            if (MODE == 0) {
                b0 = (col   < 512) ? bias0[col]   : ((col   < 1024) ? 0.0f : bias1[col - 1024]);
                b1 = (col+1 < 512) ? bias0[col+1] : ((col+1 < 1024) ? 0.0f : bias1[col+1 - 1024]);
            } else {
                b0 = bias0[col]; b1 = bias0[col+1];
            }
            float* p0 = C + (size_t)row * N + col;
            float* p1 = C + (size_t)(row + 8) * N + col;
            p0[0] = (float)acc0[mt][nt][0]*f0 + (float)acc1[mt][nt][0]*f1 + (float)acc2[mt][nt][0]*f2 + b0;
            p0[1] = (float)acc0[mt][nt][1]*f0 + (float)acc1[mt][nt][1]*f1 + (float)acc2[mt][nt][1]*f2 + b1;
            p1[0] = (float)acc0[mt][nt][2]*f0 + (float)acc1[mt][nt][2]*f1 + (float)acc2[mt][nt][2]*f2 + b0;
            p1[1] = (float)acc0[mt][nt][3]*f0 + (float)acc1[mt][nt][3]*f1 + (float)acc2[mt][nt][3]*f2 + b1;
        }
    }
}

// ---------------------------------------------------------------------------
// Fused window attention per (b,h). Register-resident S + warp softmax.
// Writes attn output as int8 hi/lo limbs (scale 2^12) for the proj GEMM.
// ---------------------------------------------------------------------------
__global__ __launch_bounds__(256) void attn_kernel(const float* __restrict__ qkv,
                                                   const float* __restrict__ mask,
                                                   char* __restrict__ ahi,
                                                   char* __restrict__ alo)
{
    const int b = blockIdx.x;
    const int h = blockIdx.y;
    const int w = b & (NW - 1);
    const int tid = threadIdx.x;
    const int wid = tid >> 5, lane = tid & 31;

    __shared__ float qs[32][64];
    __shared__ float ks[32][64];
    __shared__ float vs[64][32];
    __shared__ float Pt[64][68];
    __shared__ float qn[64], kn[64];

    const float* base = qkv + (size_t)b * NTOK * QKVCOLS + h * HDIM;
    for (int e = tid; e < NTOK * HDIM; e += 256) {
        int n = e >> 5, d = e & 31;
        const float* r = base + (size_t)n * QKVCOLS;
        qs[d][n] = r[d];
        ks[d][n] = r[512 + d];
        vs[n][d] = r[1024 + d];
    }
    __syncthreads();

    if (tid < 128) {
        int n = tid & 63;
        bool isq = tid < 64;
        float s = 0.0f;
        #pragma unroll
        for (int d = 0; d < 32; d++) {
            float x = isq ? qs[d][n] : ks[d][n];
            s = fmaf(x, x, s);
        }
        float inv = 1.0f / fmaxf(sqrtf(s), 1e-12f);
        if (isq) qn[n] = inv; else kn[n] = inv;
    }
    __syncthreads();

    float s0[8], s1[8];
    #pragma unroll
    for (int r = 0; r < 8; r++) { s0[r] = 0.0f; s1[r] = 0.0f; }
    #pragma unroll
    for (int d = 0; d < 32; d++) {
        float kv0 = ks[d][lane];
        float kv1 = ks[d][lane + 32];
        #pragma unroll
        for (int r = 0; r < 8; r++) {
            float qv = qs[d][wid*8 + r];
            s0[r] = fmaf(qv, kv0, s0[r]);
            s1[r] = fmaf(qv, kv1, s1[r]);
        }
    }

    const float scale = g_scale[h];
    const float kn0 = kn[lane], kn1 = kn[lane + 32];
    const float* rb = g_rel_bias + h * (NTOK * NTOK);
    const float* mk = mask + (size_t)w * (NTOK * NTOK);

    #pragma unroll
    for (int r = 0; r < 8; r++) {
        int n = wid*8 + r;
        float qsc = qn[n] * scale;
        int off = n*64 + lane;
        float x0 = s0[r]*qsc*kn0 + rb[off]      + mk[off];
        float x1 = s1[r]*qsc*kn1 + rb[off + 32] + mk[off + 32];
        float mx = fmaxf(x0, x1);
        #pragma unroll
        for (int o = 16; o > 0; o >>= 1)
            mx = fmaxf(mx, __shfl_xor_sync(0xffffffffu, mx, o));
        float e0 = __expf(x0 - mx);
        float e1 = __expf(x1 - mx);
        float sm = e0 + e1;
        #pragma unroll
        for (int o = 16; o > 0; o >>= 1)
            sm += __shfl_xor_sync(0xffffffffu, sm, o);
        float inv = 1.0f / sm;
        Pt[lane][n]      = e0 * inv;
        Pt[lane + 32][n] = e1 * inv;
    }
    __syncthreads();

    float o[8];
    #pragma unroll
    for (int r = 0; r < 8; r++) o[r] = 0.0f;
    #pragma unroll
    for (int m = 0; m < 64; m++) {
        float vm = vs[m][lane];
        float4 p0 = *(const float4*)&Pt[m][wid*8];
        float4 p1 = *(const float4*)&Pt[m][wid*8 + 4];
        o[0] = fmaf(p0.x, vm, o[0]);  o[1] = fmaf(p0.y, vm, o[1]);
        o[2] = fmaf(p0.z, vm, o[2]);  o[3] = fmaf(p0.w, vm, o[3]);
        o[4] = fmaf(p1.x, vm, o[4]);  o[5] = fmaf(p1.y, vm, o[5]);
        o[6] = fmaf(p1.z, vm, o[6]);  o[7] = fmaf(p1.w, vm, o[7]);
    }
    #pragma unroll
    for (int r = 0; r < 8; r++) {
        size_t oi = (size_t)(b*NTOK + wid*8 + r) * DIM + h*HDIM + lane;
        char hq, lq;
        q16_split(o[r], 4096.0f, hq, lq);
        ahi[oi] = hq;
        alo[oi] = lq;
    }
}

// ---------------------------------------------------------------------------
extern "C" void kernel_launch(void* const* d_in, const int* in_sizes, int n_in,
                              void* d_out, int out_size)
{
    const float* x           = (const float*)d_in[0];
    const float* mask        = (const float*)d_in[1];
    const float* qkv_w       = (const float*)d_in[2];
    const float* q_bias      = (const float*)d_in[3];
    const float* v_bias      = (const float*)d_in[4];
    const float* logit_scale = (const float*)d_in[5];
    const float* cpb_w1      = (const float*)d_in[6];
    const float* cpb_b1      = (const float*)d_in[7];
    const float* cpb_w2      = (const float*)d_in[8];
    const float* proj_w      = (const float*)d_in[9];
    const float* proj_b      = (const float*)d_in[10];
    const float* rel_table   = (const float*)d_in[11];
    const int*   rel_idx     = (const int*)d_in[12];
    float*       out         = (float*)d_out;

    float* qkv_ptr;
    char *xhi, *xlo, *whi, *wlo, *phi, *plo, *ahi, *alo;
    cudaGetSymbolAddress((void**)&qkv_ptr, g_qkv);
    cudaGetSymbolAddress((void**)&xhi, g_xhi); cudaGetSymbolAddress((void**)&xlo, g_xlo);
    cudaGetSymbolAddress((void**)&whi, g_whi); cudaGetSymbolAddress((void**)&wlo, g_wlo);
    cudaGetSymbolAddress((void**)&phi, g_phi); cudaGetSymbolAddress((void**)&plo, g_plo);
    cudaGetSymbolAddress((void**)&ahi, g_ahi); cudaGetSymbolAddress((void**)&alo, g_alo);

    cudaFuncSetAttribute(gemm_i8<0>, cudaFuncAttributeMaxDynamicSharedMemorySize, GEMM_SMEM);
    cudaFuncSetAttribute(gemm_i8<1>, cudaFuncAttributeMaxDynamicSharedMemorySize, GEMM_SMEM);

    // quantize inputs: activations at 2^12, weights at 2^18
    {
        int n4 = ROWS * DIM / 4;
        quant_i8<<<(n4 + 255)/256, 256>>>(x, xhi, xlo, n4, 4096.0f);
        n4 = QKVCOLS * DIM / 4;
        quant_i8<<<(n4 + 255)/256, 256>>>(qkv_w, whi, wlo, n4, 262144.0f);
        n4 = DIM * DIM / 4;
        quant_i8<<<(n4 + 255)/256, 256>>>(proj_w, phi, plo, n4, 262144.0f);
    }

    // CPB
    cpb_mlp_kernel<<<225, 512>>>(rel_table, cpb_w1, cpb_b1, cpb_w2);
    cpb_expand_kernel<<<256, 256>>>(rel_idx, logit_scale);

    // QKV GEMM: [65536,512] x [1536,512]^T -> fp32 [65536,1536]
    gemm_i8<0><<<dim3(QKVCOLS/64, ROWS/128), 256, GEMM_SMEM>>>(
        xhi, xlo, whi, wlo, q_bias, v_bias, qkv_ptr, QKVCOLS);

    // attention (writes int8 limbs)
    attn_kernel<<<dim3(BATCH, HEADS), 256>>>(qkv_ptr, mask, ahi, alo);

    // proj GEMM: [65536,512] x [512,512]^T -> d_out fp32
    gemm_i8<1><<<dim3(DIM/64, ROWS/128), 256, GEMM_SMEM>>>(
        ahi, alo, phi, plo, proj_b, nullptr, out, DIM);
}

// round 8
// speedup vs baseline: 2.4760x; 2.4760x over previous
#include <cuda_runtime.h>
#include <cuda_bf16.h>
#include <math.h>
#include <stdint.h>

#define BATCH   1024
#define NTOK    64
#define DIM     512
#define HEADS   16
#define HDIM    32
#define NW      64
#define ROWS    (BATCH * NTOK)      // 65536
#define QKVCOLS (3 * DIM)           // 1536

// ---------------- device scratch ----------------
__device__ __align__(16) float         g_qkv[(size_t)ROWS * QKVCOLS];
__device__ __align__(16) __nv_bfloat16 g_xh[(size_t)ROWS * DIM];
__device__ __align__(16) __nv_bfloat16 g_xl[(size_t)ROWS * DIM];
__device__ __align__(16) __nv_bfloat16 g_wh[(size_t)QKVCOLS * DIM];
__device__ __align__(16) __nv_bfloat16 g_wl[(size_t)QKVCOLS * DIM];
__device__ __align__(16) __nv_bfloat16 g_ph[(size_t)DIM * DIM];
__device__ __align__(16) __nv_bfloat16 g_pl[(size_t)DIM * DIM];
__device__ __align__(16) __nv_bfloat16 g_aoh[(size_t)ROWS * DIM];
__device__ __align__(16) __nv_bfloat16 g_aol[(size_t)ROWS * DIM];
__device__ float g_bias_table[225 * HEADS];
__device__ float g_rel_bias[HEADS * NTOK * NTOK];
__device__ float g_scale[HEADS];

// ---------------- helpers ----------------
__device__ __forceinline__ uint32_t smem_u32(const void* p) {
    uint32_t a;
    asm("{ .reg .u64 t; cvta.to.shared.u64 t, %1; cvt.u32.u64 %0, t; }" : "=r"(a) : "l"(p));
    return a;
}

#define LDSM4(r0,r1,r2,r3, addr) \
    asm volatile("ldmatrix.sync.aligned.m8n8.x4.shared.b16 {%0,%1,%2,%3}, [%4];" \
        : "=r"(r0),"=r"(r1),"=r"(r2),"=r"(r3) : "r"(addr))

#define MMA_BF16(d, a, b) \
    asm volatile("mma.sync.aligned.m16n8k16.row.col.f32.bf16.bf16.f32 " \
        "{%0,%1,%2,%3}, {%4,%5,%6,%7}, {%8,%9}, {%0,%1,%2,%3};" \
        : "+f"(d[0]),"+f"(d[1]),"+f"(d[2]),"+f"(d[3]) \
        : "r"(a[0]),"r"(a[1]),"r"(a[2]),"r"(a[3]),"r"(b[0]),"r"(b[1]))

#define CP16(dst, src) \
    asm volatile("cp.async.ca.shared.global [%0], [%1], 16;" :: "r"(dst), "l"(src))
#define CP_COMMIT() asm volatile("cp.async.commit_group;" ::: "memory")
#define CP_WAIT1()  asm volatile("cp.async.wait_group 1;" ::: "memory")

// ---------------- fp32 -> bf16 hi/lo split ----------------
__global__ void split_f32(const float* __restrict__ in,
                          __nv_bfloat16* __restrict__ hi,
                          __nv_bfloat16* __restrict__ lo, int n4)
{
    int i = blockIdx.x * blockDim.x + threadIdx.x;
    if (i >= n4) return;
    float4 v = ((const float4*)in)[i];
    __nv_bfloat16 h[4], l[4];
    float x[4] = {v.x, v.y, v.z, v.w};
    #pragma unroll
    for (int j = 0; j < 4; j++) {
        h[j] = __float2bfloat16(x[j]);
        l[j] = __float2bfloat16(x[j] - __bfloat162float(h[j]));
    }
    ((uint2*)hi)[i] = *(uint2*)h;
    ((uint2*)lo)[i] = *(uint2*)l;
}

// ---------------- CPB MLP ----------------
__global__ void cpb_mlp_kernel(const float* __restrict__ tbl,
                               const float* __restrict__ w1,
                               const float* __restrict__ b1,
                               const float* __restrict__ w2)
{
    int i = blockIdx.x, j = threadIdx.x;
    __shared__ float hid[512];
    float hv = tbl[i*2+0] * w1[j*2+0] + tbl[i*2+1] * w1[j*2+1] + b1[j];
    hid[j] = fmaxf(hv, 0.0f);
    __syncthreads();
    int warp = j >> 5, lane = j & 31;
    float s = 0.0f;
    #pragma unroll
    for (int c = lane; c < 512; c += 32) s += hid[c] * w2[warp*512 + c];
    #pragma unroll
    for (int off = 16; off > 0; off >>= 1) s += __shfl_xor_sync(0xffffffffu, s, off);
    if (lane == 0) g_bias_table[i*HEADS + warp] = s;
}

__global__ void cpb_expand_kernel(const int* __restrict__ idx,
                                  const float* __restrict__ logit_scale)
{
    int g = blockIdx.x * 256 + threadIdx.x;
    int h = g >> 12, nm = g & 4095;
    float v = g_bias_table[idx[nm]*HEADS + h];
    g_rel_bias[g] = 16.0f / (1.0f + expf(-v));
    if (g < HEADS) g_scale[g] = expf(fminf(logit_scale[g], 4.60517018598809136804f));
}

// ---------------------------------------------------------------------------
// split-bf16 GEMM (NT): C[M,N] = (Ah+Al)[M,K] @ (Bh+Bl)[N,K]^T + bias
// BM=128 BN=128 BK=32, K=512. 512 thr = 16 warps (4m x 4n), warp 32x32.
// 3-stage cp.async pipeline. smem rows padded to 80B (conflict-free LDSM).
// stage layout: [Ah 10240 | Al 10240 | Bh 10240 | Bl 10240] = 40960 B
// ---------------------------------------------------------------------------
#define AB_SZ 10240
#define STG (4 * AB_SZ)          // 40960
#define GEMM_SMEM (3 * STG)      // 122880

template <int MODE>   // 0: qkv bias (q|0|v), 1: proj bias
__global__ __launch_bounds__(512, 1) void gemm_bf16_128(
    const __nv_bfloat16* __restrict__ Ah, const __nv_bfloat16* __restrict__ Al,
    const __nv_bfloat16* __restrict__ Bh, const __nv_bfloat16* __restrict__ Bl,
    const float* __restrict__ bias0, const float* __restrict__ bias1,
    float* __restrict__ C, int N)
{
    extern __shared__ char smem[];

    const int tid  = threadIdx.x;
    const int bm   = blockIdx.y * 128;
    const int bn   = blockIdx.x * 128;
    const int wid  = tid >> 5, lane = tid & 31;
    const int wm   = (wid & 3) * 32;
    const int wn   = (wid >> 2) * 32;

    const uint32_t sbase = smem_u32(smem);

    float acc[2][4][4];
    #pragma unroll
    for (int a = 0; a < 2; a++)
        #pragma unroll
        for (int b = 0; b < 4; b++)
            #pragma unroll
            for (int c = 0; c < 4; c++) acc[a][b][c] = 0.0f;

    // --- stage loader: each thread loads 4 chunks of 16B (one per buffer) ---
    const int lrow = tid >> 2;       // 0..127
    const int lq   = tid & 3;        // 0..3
    auto load_stage = [&](int kt, int buf) {
        const uint32_t sb = sbase + buf * STG;
        const size_t goff_a = (size_t)(bm + lrow) * 512 + kt * 32 + lq * 8;
        const size_t goff_b = (size_t)(bn + lrow) * 512 + kt * 32 + lq * 8;
        const uint32_t d = sb + (uint32_t)(lrow * 80 + lq * 16);
        CP16(d,             (const char*)Ah + goff_a * 2);
        CP16(d +   AB_SZ,   (const char*)Al + goff_a * 2);
        CP16(d + 2*AB_SZ,   (const char*)Bh + goff_b * 2);
        CP16(d + 3*AB_SZ,   (const char*)Bl + goff_b * 2);
        CP_COMMIT();
    };

    load_stage(0, 0);
    load_stage(1, 1);

    for (int kt = 0; kt < 16; kt++) {
        const int buf = kt % 3;
        CP_WAIT1();
        __syncthreads();

        if (kt + 2 < 16) load_stage(kt + 2, (kt + 2) % 3);
        else CP_COMMIT();

        const uint32_t sb  = sbase + buf * STG;
        const uint32_t aAh = sb;
        const uint32_t aAl = sb +   AB_SZ;
        const uint32_t aBh = sb + 2*AB_SZ;
        const uint32_t aBl = sb + 3*AB_SZ;

        #pragma unroll
        for (int ks = 0; ks < 2; ks++) {
            const int kb = ks * 16;
            uint32_t ah[2][4], al[2][4], bh[4][2], bl[4][2];
            #pragma unroll
            for (int mt = 0; mt < 2; mt++) {
                int row = wm + mt*16 + (lane & 15);
                int col = kb + (lane >> 4) * 8;
                uint32_t off = (uint32_t)(row*80 + col*2);
                LDSM4(ah[mt][0], ah[mt][1], ah[mt][2], ah[mt][3], aAh + off);
                LDSM4(al[mt][0], al[mt][1], al[mt][2], al[mt][3], aAl + off);
            }
            #pragma unroll
            for (int np = 0; np < 2; np++) {
                int g = lane >> 3;
                int row = wn + np*16 + (lane & 7) + ((g >> 1) & 1) * 8;
                int col = kb + (g & 1) * 8;
                uint32_t off = (uint32_t)(row*80 + col*2);
                LDSM4(bh[2*np][0], bh[2*np][1], bh[2*np+1][0], bh[2*np+1][1], aBh + off);
                LDSM4(bl[2*np][0], bl[2*np][1], bl[2*np+1][0], bl[2*np+1][1], aBl + off);
            }
            #pragma unroll
            for (int mt = 0; mt < 2; mt++)
                #pragma unroll
                for (int nt = 0; nt < 4; nt++) {
                    MMA_BF16(acc[mt][nt], ah[mt], bh[nt]);
                    MMA_BF16(acc[mt][nt], ah[mt], bl[nt]);
                    MMA_BF16(acc[mt][nt], al[mt], bh[nt]);
                }
        }
        __syncthreads();
    }

    // ---- epilogue ----
    #pragma unroll
    for (int mt = 0; mt < 2; mt++) {
        #pragma unroll
        for (int nt = 0; nt < 4; nt++) {
            int row = bm + wm + mt*16 + (lane >> 2);
            int col = bn + wn + nt*8 + (lane & 3)*2;
            float b0, b1;
            if (MODE == 0) {
                b0 = (col   < 512) ? bias0[col]   : ((col   < 1024) ? 0.0f : bias1[col - 1024]);
                b1 = (col+1 < 512) ? bias0[col+1] : ((col+1 < 1024) ? 0.0f : bias1[col+1 - 1024]);
            } else {
                b0 = bias0[col]; b1 = bias0[col+1];
            }
            float* p0 = C + (size_t)row * N + col;
            float* p1 = C + (size_t)(row + 8) * N + col;
            p0[0] = acc[mt][nt][0] + b0;  p0[1] = acc[mt][nt][1] + b1;
            p1[0] = acc[mt][nt][2] + b0;  p1[1] = acc[mt][nt][3] + b1;
        }
    }
}

// ---------------------------------------------------------------------------
// Fused window attention per (b,h). Register-resident S + warp softmax.
// Pt stored with 8-col XOR swizzle (4-way instead of 8-way store conflicts).
// Writes attn output as bf16 hi/lo for the 3-term proj GEMM.
// ---------------------------------------------------------------------------
__global__ __launch_bounds__(256) void attn_kernel(const float* __restrict__ qkv,
                                                   const float* __restrict__ mask,
                                                   __nv_bfloat16* __restrict__ aoh,
                                                   __nv_bfloat16* __restrict__ aol)
{
    const int b = blockIdx.x;
    const int h = blockIdx.y;
    const int w = b & (NW - 1);
    const int tid = threadIdx.x;
    const int wid = tid >> 5, lane = tid & 31;

    __shared__ float qs[32][64];
    __shared__ float ks[32][64];
    __shared__ float vs[64][32];
    __shared__ float Pt[64][68];    // logical [m][n], cols swizzled in 8-blocks
    __shared__ float qn[64], kn[64];

    const float* base = qkv + (size_t)b * NTOK * QKVCOLS + h * HDIM;
    for (int e = tid; e < NTOK * HDIM; e += 256) {
        int n = e >> 5, d = e & 31;
        const float* r = base + (size_t)n * QKVCOLS;
        qs[d][n] = r[d];
        ks[d][n] = r[512 + d];
        vs[n][d] = r[1024 + d];
    }
    __syncthreads();

    if (tid < 128) {
        int n = tid & 63;
        bool isq = tid < 64;
        float s = 0.0f;
        #pragma unroll
        for (int d = 0; d < 32; d++) {
            float x = isq ? qs[d][n] : ks[d][n];
            s = fmaf(x, x, s);
        }
        float inv = 1.0f / fmaxf(sqrtf(s), 1e-12f);
        if (isq) qn[n] = inv; else kn[n] = inv;
    }
    __syncthreads();

    float s0[8], s1[8];
    #pragma unroll
    for (int r = 0; r < 8; r++) { s0[r] = 0.0f; s1[r] = 0.0f; }
    #pragma unroll
    for (int d = 0; d < 32; d++) {
        float kv0 = ks[d][lane];
        float kv1 = ks[d][lane + 32];
        #pragma unroll
        for (int r = 0; r < 8; r++) {
            float qv = qs[d][wid*8 + r];
            s0[r] = fmaf(qv, kv0, s0[r]);
            s1[r] = fmaf(qv, kv1, s1[r]);
        }
    }

    const float scale = g_scale[h];
    const float kn0 = kn[lane], kn1 = kn[lane + 32];
    const float* rb = g_rel_bias + h * (NTOK * NTOK);
    const float* mk = mask + (size_t)w * (NTOK * NTOK);

    const int swz0 = (lane & 7) << 3;          // swizzle for row 'lane'
    const int swz1 = ((lane + 32) & 7) << 3;   // swizzle for row 'lane+32'
    #pragma unroll
    for (int r = 0; r < 8; r++) {
        int n = wid*8 + r;
        float qsc = qn[n] * scale;
        int off = n*64 + lane;
        float x0 = s0[r]*qsc*kn0 + rb[off]      + mk[off];
        float x1 = s1[r]*qsc*kn1 + rb[off + 32] + mk[off + 32];
        float mx = fmaxf(x0, x1);
        #pragma unroll
        for (int o = 16; o > 0; o >>= 1)
            mx = fmaxf(mx, __shfl_xor_sync(0xffffffffu, mx, o));
        float e0 = __expf(x0 - mx);
        float e1 = __expf(x1 - mx);
        float sm = e0 + e1;
        #pragma unroll
        for (int o = 16; o > 0; o >>= 1)
            sm += __shfl_xor_sync(0xffffffffu, sm, o);
        float inv = 1.0f / sm;
        Pt[lane]     [n ^ swz0] = e0 * inv;
        Pt[lane + 32][n ^ swz1] = e1 * inv;
    }
    __syncthreads();

    float o[8];
    #pragma unroll
    for (int r = 0; r < 8; r++) o[r] = 0.0f;
    #pragma unroll
    for (int m = 0; m < 64; m++) {
        float vm = vs[m][lane];
        const float* prow = &Pt[m][(wid ^ (m & 7)) * 8];
        float4 p0 = *(const float4*)(prow);
        float4 p1 = *(const float4*)(prow + 4);
        o[0] = fmaf(p0.x, vm, o[0]);  o[1] = fmaf(p0.y, vm, o[1]);
        o[2] = fmaf(p0.z, vm, o[2]);  o[3] = fmaf(p0.w, vm, o[3]);
        o[4] = fmaf(p1.x, vm, o[4]);  o[5] = fmaf(p1.y, vm, o[5]);
        o[6] = fmaf(p1.z, vm, o[6]);  o[7] = fmaf(p1.w, vm, o[7]);
    }
    #pragma unroll
    for (int r = 0; r < 8; r++) {
        size_t oi = (size_t)(b*NTOK + wid*8 + r) * DIM + h*HDIM + lane;
        __nv_bfloat16 hi = __float2bfloat16(o[r]);
        __nv_bfloat16 lo = __float2bfloat16(o[r] - __bfloat162float(hi));
        aoh[oi] = hi;
        aol[oi] = lo;
    }
}

// ---------------------------------------------------------------------------
extern "C" void kernel_launch(void* const* d_in, const int* in_sizes, int n_in,
                              void* d_out, int out_size)
{
    const float* x           = (const float*)d_in[0];
    const float* mask        = (const float*)d_in[1];
    const float* qkv_w       = (const float*)d_in[2];
    const float* q_bias      = (const float*)d_in[3];
    const float* v_bias      = (const float*)d_in[4];
    const float* logit_scale = (const float*)d_in[5];
    const float* cpb_w1      = (const float*)d_in[6];
    const float* cpb_b1      = (const float*)d_in[7];
    const float* cpb_w2      = (const float*)d_in[8];
    const float* proj_w      = (const float*)d_in[9];
    const float* proj_b      = (const float*)d_in[10];
    const float* rel_table   = (const float*)d_in[11];
    const int*   rel_idx     = (const int*)d_in[12];
    float*       out         = (float*)d_out;

    float *qkv_ptr;
    __nv_bfloat16 *xh, *xl, *wh, *wl, *ph, *pl, *aoh, *aol;
    cudaGetSymbolAddress((void**)&qkv_ptr, g_qkv);
    cudaGetSymbolAddress((void**)&xh, g_xh);   cudaGetSymbolAddress((void**)&xl, g_xl);
    cudaGetSymbolAddress((void**)&wh, g_wh);   cudaGetSymbolAddress((void**)&wl, g_wl);
    cudaGetSymbolAddress((void**)&ph, g_ph);   cudaGetSymbolAddress((void**)&pl, g_pl);
    cudaGetSymbolAddress((void**)&aoh, g_aoh); cudaGetSymbolAddress((void**)&aol, g_aol);

    cudaFuncSetAttribute(gemm_bf16_128<0>, cudaFuncAttributeMaxDynamicSharedMemorySize, GEMM_SMEM);
    cudaFuncSetAttribute(gemm_bf16_128<1>, cudaFuncAttributeMaxDynamicSharedMemorySize, GEMM_SMEM);

    // splits
    {
        int n4 = ROWS * DIM / 4;
        split_f32<<<(n4 + 255)/256, 256>>>(x, xh, xl, n4);
        n4 = QKVCOLS * DIM / 4;
        split_f32<<<(n4 + 255)/256, 256>>>(qkv_w, wh, wl, n4);
        n4 = DIM * DIM / 4;
        split_f32<<<(n4 + 255)/256, 256>>>(proj_w, ph, pl, n4);
    }

    // CPB
    cpb_mlp_kernel<<<225, 512>>>(rel_table, cpb_w1, cpb_b1, cpb_w2);
    cpb_expand_kernel<<<256, 256>>>(rel_idx, logit_scale);

    // QKV GEMM: [65536,512] x [1536,512]^T -> fp32 [65536,1536]
    gemm_bf16_128<0><<<dim3(QKVCOLS/128, ROWS/128), 512, GEMM_SMEM>>>(
        xh, xl, wh, wl, q_bias, v_bias, qkv_ptr, QKVCOLS);

    // attention (writes bf16 hi/lo)
    attn_kernel<<<dim3(BATCH, HEADS), 256>>>(qkv_ptr, mask, aoh, aol);

    // proj GEMM: [65536,512] x [512,512]^T -> d_out fp32
    gemm_bf16_128<1><<<dim3(DIM/128, ROWS/128), 512, GEMM_SMEM>>>(
        aoh, aol, ph, pl, proj_b, nullptr, out, DIM);
}

// round 9
// speedup vs baseline: 2.8178x; 1.1380x over previous
#include <cuda_runtime.h>
#include <cuda_bf16.h>
#include <math.h>
#include <stdint.h>

#define BATCH   1024
#define NTOK    64
#define DIM     512
#define HEADS   16
#define HDIM    32
#define NW      64
#define ROWS    (BATCH * NTOK)      // 65536
#define QKVCOLS (3 * DIM)           // 1536

// ---------------- device scratch ----------------
__device__ __align__(16) float         g_qkv[(size_t)ROWS * QKVCOLS];
__device__ __align__(16) __nv_bfloat16 g_xh[(size_t)ROWS * DIM];
__device__ __align__(16) __nv_bfloat16 g_xl[(size_t)ROWS * DIM];
__device__ __align__(16) __nv_bfloat16 g_wh[(size_t)QKVCOLS * DIM];
__device__ __align__(16) __nv_bfloat16 g_wl[(size_t)QKVCOLS * DIM];
__device__ __align__(16) __nv_bfloat16 g_ph[(size_t)DIM * DIM];
__device__ __align__(16) __nv_bfloat16 g_pl[(size_t)DIM * DIM];
__device__ __align__(16) __nv_bfloat16 g_aoh[(size_t)ROWS * DIM];
__device__ __align__(16) __nv_bfloat16 g_aol[(size_t)ROWS * DIM];
__device__ float g_bias_table[225 * HEADS];
__device__ float g_rel_bias[HEADS * NTOK * NTOK];
__device__ float g_scale[HEADS];

// ---------------- helpers ----------------
__device__ __forceinline__ uint32_t smem_u32(const void* p) {
    uint32_t a;
    asm("{ .reg .u64 t; cvta.to.shared.u64 t, %1; cvt.u32.u64 %0, t; }" : "=r"(a) : "l"(p));
    return a;
}

#define LDSM4(r0,r1,r2,r3, addr) \
    asm volatile("ldmatrix.sync.aligned.m8n8.x4.shared.b16 {%0,%1,%2,%3}, [%4];" \
        : "=r"(r0),"=r"(r1),"=r"(r2),"=r"(r3) : "r"(addr))

#define MMA_BF16(d, a, b) \
    asm volatile("mma.sync.aligned.m16n8k16.row.col.f32.bf16.bf16.f32 " \
        "{%0,%1,%2,%3}, {%4,%5,%6,%7}, {%8,%9}, {%0,%1,%2,%3};" \
        : "+f"(d[0]),"+f"(d[1]),"+f"(d[2]),"+f"(d[3]) \
        : "r"(a[0]),"r"(a[1]),"r"(a[2]),"r"(a[3]),"r"(b[0]),"r"(b[1]))

#define CP16(dst, src) \
    asm volatile("cp.async.ca.shared.global [%0], [%1], 16;" :: "r"(dst), "l"(src))
#define CP_COMMIT() asm volatile("cp.async.commit_group;" ::: "memory")
#define CP_WAIT1()  asm volatile("cp.async.wait_group 1;" ::: "memory")

// ---------------- fp32 -> bf16 hi/lo split ----------------
__global__ void split_f32(const float* __restrict__ in,
                          __nv_bfloat16* __restrict__ hi,
                          __nv_bfloat16* __restrict__ lo, int n4)
{
    int i = blockIdx.x * blockDim.x + threadIdx.x;
    if (i >= n4) return;
    float4 v = ((const float4*)in)[i];
    __nv_bfloat16 h[4], l[4];
    float x[4] = {v.x, v.y, v.z, v.w};
    #pragma unroll
    for (int j = 0; j < 4; j++) {
        h[j] = __float2bfloat16(x[j]);
        l[j] = __float2bfloat16(x[j] - __bfloat162float(h[j]));
    }
    ((uint2*)hi)[i] = *(uint2*)h;
    ((uint2*)lo)[i] = *(uint2*)l;
}

// ---------------- CPB MLP ----------------
__global__ void cpb_mlp_kernel(const float* __restrict__ tbl,
                               const float* __restrict__ w1,
                               const float* __restrict__ b1,
                               const float* __restrict__ w2)
{
    int i = blockIdx.x, j = threadIdx.x;
    __shared__ float hid[512];
    float hv = tbl[i*2+0] * w1[j*2+0] + tbl[i*2+1] * w1[j*2+1] + b1[j];
    hid[j] = fmaxf(hv, 0.0f);
    __syncthreads();
    int warp = j >> 5, lane = j & 31;
    float s = 0.0f;
    #pragma unroll
    for (int c = lane; c < 512; c += 32) s += hid[c] * w2[warp*512 + c];
    #pragma unroll
    for (int off = 16; off > 0; off >>= 1) s += __shfl_xor_sync(0xffffffffu, s, off);
    if (lane == 0) g_bias_table[i*HEADS + warp] = s;
}

__global__ void cpb_expand_kernel(const int* __restrict__ idx,
                                  const float* __restrict__ logit_scale)
{
    int g = blockIdx.x * 256 + threadIdx.x;
    int h = g >> 12, nm = g & 4095;
    float v = g_bias_table[idx[nm]*HEADS + h];
    g_rel_bias[g] = 16.0f / (1.0f + expf(-v));
    if (g < HEADS) g_scale[g] = expf(fminf(logit_scale[g], 4.60517018598809136804f));
}

// ---------------------------------------------------------------------------
// split-bf16 GEMM (NT): C[M,N] = (Ah+Al)[M,K] @ (Bh+Bl)[N,K]^T + bias
// BM=128 BN=128 BK=32, K=512. 512 thr = 16 warps (4m x 4n), warp 32x32.
// 3-stage cp.async pipeline. smem rows padded to 80B (conflict-free LDSM).
// ---------------------------------------------------------------------------
#define AB_SZ 10240
#define STG (4 * AB_SZ)          // 40960
#define GEMM_SMEM (3 * STG)      // 122880

template <int MODE>   // 0: qkv bias (q|0|v), 1: proj bias
__global__ __launch_bounds__(512, 1) void gemm_bf16_128(
    const __nv_bfloat16* __restrict__ Ah, const __nv_bfloat16* __restrict__ Al,
    const __nv_bfloat16* __restrict__ Bh, const __nv_bfloat16* __restrict__ Bl,
    const float* __restrict__ bias0, const float* __restrict__ bias1,
    float* __restrict__ C, int N)
{
    extern __shared__ char smem[];

    const int tid  = threadIdx.x;
    const int bm   = blockIdx.y * 128;
    const int bn   = blockIdx.x * 128;
    const int wid  = tid >> 5, lane = tid & 31;
    const int wm   = (wid & 3) * 32;
    const int wn   = (wid >> 2) * 32;

    const uint32_t sbase = smem_u32(smem);

    float acc[2][4][4];
    #pragma unroll
    for (int a = 0; a < 2; a++)
        #pragma unroll
        for (int b = 0; b < 4; b++)
            #pragma unroll
            for (int c = 0; c < 4; c++) acc[a][b][c] = 0.0f;

    const int lrow = tid >> 2;       // 0..127
    const int lq   = tid & 3;        // 0..3
    auto load_stage = [&](int kt, int buf) {
        const uint32_t sb = sbase + buf * STG;
        const size_t goff_a = (size_t)(bm + lrow) * 512 + kt * 32 + lq * 8;
        const size_t goff_b = (size_t)(bn + lrow) * 512 + kt * 32 + lq * 8;
        const uint32_t d = sb + (uint32_t)(lrow * 80 + lq * 16);
        CP16(d,             (const char*)Ah + goff_a * 2);
        CP16(d +   AB_SZ,   (const char*)Al + goff_a * 2);
        CP16(d + 2*AB_SZ,   (const char*)Bh + goff_b * 2);
        CP16(d + 3*AB_SZ,   (const char*)Bl + goff_b * 2);
        CP_COMMIT();
    };

    load_stage(0, 0);
    load_stage(1, 1);

    for (int kt = 0; kt < 16; kt++) {
        const int buf = kt % 3;
        CP_WAIT1();
        __syncthreads();

        if (kt + 2 < 16) load_stage(kt + 2, (kt + 2) % 3);
        else CP_COMMIT();

        const uint32_t sb  = sbase + buf * STG;
        const uint32_t aAh = sb;
        const uint32_t aAl = sb +   AB_SZ;
        const uint32_t aBh = sb + 2*AB_SZ;
        const uint32_t aBl = sb + 3*AB_SZ;

        #pragma unroll
        for (int ks = 0; ks < 2; ks++) {
            const int kb = ks * 16;
            uint32_t ah[2][4], al[2][4], bh[4][2], bl[4][2];
            #pragma unroll
            for (int mt = 0; mt < 2; mt++) {
                int row = wm + mt*16 + (lane & 15);
                int col = kb + (lane >> 4) * 8;
                uint32_t off = (uint32_t)(row*80 + col*2);
                LDSM4(ah[mt][0], ah[mt][1], ah[mt][2], ah[mt][3], aAh + off);
                LDSM4(al[mt][0], al[mt][1], al[mt][2], al[mt][3], aAl + off);
            }
            #pragma unroll
            for (int np = 0; np < 2; np++) {
                int g = lane >> 3;
                int row = wn + np*16 + (lane & 7) + ((g >> 1) & 1) * 8;
                int col = kb + (g & 1) * 8;
                uint32_t off = (uint32_t)(row*80 + col*2);
                LDSM4(bh[2*np][0], bh[2*np][1], bh[2*np+1][0], bh[2*np+1][1], aBh + off);
                LDSM4(bl[2*np][0], bl[2*np][1], bl[2*np+1][0], bl[2*np+1][1], aBl + off);
            }
            #pragma unroll
            for (int mt = 0; mt < 2; mt++)
                #pragma unroll
                for (int nt = 0; nt < 4; nt++) {
                    MMA_BF16(acc[mt][nt], ah[mt], bh[nt]);
                    MMA_BF16(acc[mt][nt], ah[mt], bl[nt]);
                    MMA_BF16(acc[mt][nt], al[mt], bh[nt]);
                }
        }
        __syncthreads();
    }

    #pragma unroll
    for (int mt = 0; mt < 2; mt++) {
        #pragma unroll
        for (int nt = 0; nt < 4; nt++) {
            int row = bm + wm + mt*16 + (lane >> 2);
            int col = bn + wn + nt*8 + (lane & 3)*2;
            float b0, b1;
            if (MODE == 0) {
                b0 = (col   < 512) ? bias0[col]   : ((col   < 1024) ? 0.0f : bias1[col - 1024]);
                b1 = (col+1 < 512) ? bias0[col+1] : ((col+1 < 1024) ? 0.0f : bias1[col+1 - 1024]);
            } else {
                b0 = bias0[col]; b1 = bias0[col+1];
            }
            float* p0 = C + (size_t)row * N + col;
            float* p1 = C + (size_t)(row + 8) * N + col;
            p0[0] = acc[mt][nt][0] + b0;  p0[1] = acc[mt][nt][1] + b1;
            p1[0] = acc[mt][nt][2] + b0;  p1[1] = acc[mt][nt][3] + b1;
        }
    }
}

// ---------------------------------------------------------------------------
// Fused window attention per (b,h). q/k staged [token][d] (float4 S-loop, 4x
// fewer LDS wavefronts), register-resident S + warp softmax, swizzled Pt.
// Writes attn output as bf16 hi/lo for the 3-term proj GEMM.
// ---------------------------------------------------------------------------
__global__ __launch_bounds__(256) void attn_kernel(const float* __restrict__ qkv,
                                                   const float* __restrict__ mask,
                                                   __nv_bfloat16* __restrict__ aoh,
                                                   __nv_bfloat16* __restrict__ aol)
{
    const int b = blockIdx.x;
    const int h = blockIdx.y;
    const int w = b & (NW - 1);
    const int tid = threadIdx.x;
    const int wid = tid >> 5, lane = tid & 31;

    __shared__ __align__(16) float qs[64][36];   // [token][d], 144B rows
    __shared__ __align__(16) float ks[64][36];
    __shared__ __align__(16) float vs[64][32];
    __shared__ __align__(16) float Pt[64][68];   // swizzled cols (8-blocks)
    __shared__ float qn[64], kn[64];

    // load: warp wid handles token rows wid, wid+8, ... (lane = d) — conflict-free
    const float* base = qkv + (size_t)b * NTOK * QKVCOLS + h * HDIM;
    #pragma unroll
    for (int i = 0; i < 8; i++) {
        int n = wid + i * 8;
        const float* r = base + (size_t)n * QKVCOLS;
        qs[n][lane] = r[lane];
        ks[n][lane] = r[512 + lane];
        vs[n][lane] = r[1024 + lane];
    }
    __syncthreads();

    // inverse norms: rows are contiguous now
    if (tid < 128) {
        int n = tid & 63;
        bool isq = tid < 64;
        const float4* rr = (const float4*)(isq ? &qs[n][0] : &ks[n][0]);
        float s = 0.0f;
        #pragma unroll
        for (int j = 0; j < 8; j++) {
            float4 v = rr[j];
            s = fmaf(v.x, v.x, s); s = fmaf(v.y, v.y, s);
            s = fmaf(v.z, v.z, s); s = fmaf(v.w, v.w, s);
        }
        float inv = 1.0f / fmaxf(sqrtf(s), 1e-12f);
        if (isq) qn[n] = inv; else kn[n] = inv;
    }
    __syncthreads();

    // S: warp wid owns rows n = wid*8..+7; lane owns cols m = lane, lane+32
    float s0[8], s1[8];
    #pragma unroll
    for (int r = 0; r < 8; r++) { s0[r] = 0.0f; s1[r] = 0.0f; }
    #pragma unroll
    for (int d4 = 0; d4 < 32; d4 += 4) {
        float4 kv0 = *(const float4*)&ks[lane][d4];
        float4 kv1 = *(const float4*)&ks[lane + 32][d4];
        #pragma unroll
        for (int r = 0; r < 8; r++) {
            float4 qv = *(const float4*)&qs[wid*8 + r][d4];   // broadcast
            s0[r] = fmaf(qv.x, kv0.x, s0[r]);
            s0[r] = fmaf(qv.y, kv0.y, s0[r]);
            s0[r] = fmaf(qv.z, kv0.z, s0[r]);
            s0[r] = fmaf(qv.w, kv0.w, s0[r]);
            s1[r] = fmaf(qv.x, kv1.x, s1[r]);
            s1[r] = fmaf(qv.y, kv1.y, s1[r]);
            s1[r] = fmaf(qv.z, kv1.z, s1[r]);
            s1[r] = fmaf(qv.w, kv1.w, s1[r]);
        }
    }

    const float scale = g_scale[h];
    const float kn0 = kn[lane], kn1 = kn[lane + 32];
    const float* rb = g_rel_bias + h * (NTOK * NTOK);
    const float* mk = mask + (size_t)w * (NTOK * NTOK);

    const int swz0 = (lane & 7) << 3;
    const int swz1 = ((lane + 32) & 7) << 3;
    #pragma unroll
    for (int r = 0; r < 8; r++) {
        int n = wid*8 + r;
        float qsc = qn[n] * scale;
        int off = n*64 + lane;
        float x0 = s0[r]*qsc*kn0 + rb[off]      + mk[off];
        float x1 = s1[r]*qsc*kn1 + rb[off + 32] + mk[off + 32];
        float mx = fmaxf(x0, x1);
        #pragma unroll
        for (int o = 16; o > 0; o >>= 1)
            mx = fmaxf(mx, __shfl_xor_sync(0xffffffffu, mx, o));
        float e0 = __expf(x0 - mx);
        float e1 = __expf(x1 - mx);
        float sm = e0 + e1;
        #pragma unroll
        for (int o = 16; o > 0; o >>= 1)
            sm += __shfl_xor_sync(0xffffffffu, sm, o);
        float inv = 1.0f / sm;
        Pt[lane]     [n ^ swz0] = e0 * inv;
        Pt[lane + 32][n ^ swz1] = e1 * inv;
    }
    __syncthreads();

    // PV: warp wid rows n = wid*8..+7; lane owns col d = lane
    float o[8];
    #pragma unroll
    for (int r = 0; r < 8; r++) o[r] = 0.0f;
    #pragma unroll
    for (int m = 0; m < 64; m++) {
        float vm = vs[m][lane];
        const float* prow = &Pt[m][(wid ^ (m & 7)) * 8];
        float4 p0 = *(const float4*)(prow);
        float4 p1 = *(const float4*)(prow + 4);
        o[0] = fmaf(p0.x, vm, o[0]);  o[1] = fmaf(p0.y, vm, o[1]);
        o[2] = fmaf(p0.z, vm, o[2]);  o[3] = fmaf(p0.w, vm, o[3]);
        o[4] = fmaf(p1.x, vm, o[4]);  o[5] = fmaf(p1.y, vm, o[5]);
        o[6] = fmaf(p1.z, vm, o[6]);  o[7] = fmaf(p1.w, vm, o[7]);
    }
    #pragma unroll
    for (int r = 0; r < 8; r++) {
        size_t oi = (size_t)(b*NTOK + wid*8 + r) * DIM + h*HDIM + lane;
        __nv_bfloat16 hi = __float2bfloat16(o[r]);
        __nv_bfloat16 lo = __float2bfloat16(o[r] - __bfloat162float(hi));
        aoh[oi] = hi;
        aol[oi] = lo;
    }
}

// ---------------------------------------------------------------------------
extern "C" void kernel_launch(void* const* d_in, const int* in_sizes, int n_in,
                              void* d_out, int out_size)
{
    const float* x           = (const float*)d_in[0];
    const float* mask        = (const float*)d_in[1];
    const float* qkv_w       = (const float*)d_in[2];
    const float* q_bias      = (const float*)d_in[3];
    const float* v_bias      = (const float*)d_in[4];
    const float* logit_scale = (const float*)d_in[5];
    const float* cpb_w1      = (const float*)d_in[6];
    const float* cpb_b1      = (const float*)d_in[7];
    const float* cpb_w2      = (const float*)d_in[8];
    const float* proj_w      = (const float*)d_in[9];
    const float* proj_b      = (const float*)d_in[10];
    const float* rel_table   = (const float*)d_in[11];
    const int*   rel_idx     = (const int*)d_in[12];
    float*       out         = (float*)d_out;

    float *qkv_ptr;
    __nv_bfloat16 *xh, *xl, *wh, *wl, *ph, *pl, *aoh, *aol;
    cudaGetSymbolAddress((void**)&qkv_ptr, g_qkv);
    cudaGetSymbolAddress((void**)&xh, g_xh);   cudaGetSymbolAddress((void**)&xl, g_xl);
    cudaGetSymbolAddress((void**)&wh, g_wh);   cudaGetSymbolAddress((void**)&wl, g_wl);
    cudaGetSymbolAddress((void**)&ph, g_ph);   cudaGetSymbolAddress((void**)&pl, g_pl);
    cudaGetSymbolAddress((void**)&aoh, g_aoh); cudaGetSymbolAddress((void**)&aol, g_aol);

    cudaFuncSetAttribute(gemm_bf16_128<0>, cudaFuncAttributeMaxDynamicSharedMemorySize, GEMM_SMEM);
    cudaFuncSetAttribute(gemm_bf16_128<1>, cudaFuncAttributeMaxDynamicSharedMemorySize, GEMM_SMEM);

    // splits
    {
        int n4 = ROWS * DIM / 4;
        split_f32<<<(n4 + 255)/256, 256>>>(x, xh, xl, n4);
        n4 = QKVCOLS * DIM / 4;
        split_f32<<<(n4 + 255)/256, 256>>>(qkv_w, wh, wl, n4);
        n4 = DIM * DIM / 4;
        split_f32<<<(n4 + 255)/256, 256>>>(proj_w, ph, pl, n4);
    }

    // CPB
    cpb_mlp_kernel<<<225, 512>>>(rel_table, cpb_w1, cpb_b1, cpb_w2);
    cpb_expand_kernel<<<256, 256>>>(rel_idx, logit_scale);

    // QKV GEMM: [65536,512] x [1536,512]^T -> fp32 [65536,1536]
    gemm_bf16_128<0><<<dim3(QKVCOLS/128, ROWS/128), 512, GEMM_SMEM>>>(
        xh, xl, wh, wl, q_bias, v_bias, qkv_ptr, QKVCOLS);

    // attention (writes bf16 hi/lo)
    attn_kernel<<<dim3(BATCH, HEADS), 256>>>(qkv_ptr, mask, aoh, aol);

    // proj GEMM: [65536,512] x [512,512]^T -> d_out fp32
    gemm_bf16_128<1><<<dim3(DIM/128, ROWS/128), 512, GEMM_SMEM>>>(
        aoh, aol, ph, pl, proj_b, nullptr, out, DIM);
}